// round 6
// baseline (speedup 1.0000x reference)
#include <cuda_runtime.h>
#include <cuda_bf16.h>
#include <cuda_fp8.h>
#include <cuda_fp16.h>
#include <math.h>

// Problem constants (fixed shapes from reference)
#define NLAYER   12
#define BS       2048          // B*S
#define DDIM     1024
#define NPAIR    2048
#define KNEG     5
#define INV_TEMP 10.0f         // 1 / 0.1
#define EPSN     1e-8f
#define TOTAL_PAIRS (NLAYER * NPAIR)                 // 24576
#define TOTAL_ROWS  (NLAYER * BS)                    // 24576 rows of 1024
#define TOTAL_ELEMS ((size_t)TOTAL_ROWS * DDIM)      // 25,165,824

// Static scratch (no runtime allocation).
__device__ unsigned char g_actn_fp8[TOTAL_ELEMS];    // normalized rows, e4m3, 24 MiB
__device__ float         g_contrib[TOTAL_PAIRS];     // per-(l,n) loss terms

// ---------------------------------------------------------------------------
// Pass 1: per-row L2-normalize in fp32 (exact, reference-faithful), then
// round the unit vector to e4m3. One warp per row: 1024 floats = 256 float4;
// 32 lanes x 8 iters, fully coalesced. HBM-streaming bound (~16 us).
// ---------------------------------------------------------------------------
__global__ void __launch_bounds__(256)
norm_cvt_kernel(const float* __restrict__ act)
{
    const int row  = (blockIdx.x * blockDim.x + threadIdx.x) >> 5;
    const int lane = threadIdx.x & 31;
    if (row >= TOTAL_ROWS) return;

    const float4* __restrict__ src = (const float4*)(act + (size_t)row * DDIM);

    float4 v[8];
    float ss = 0.f;
#pragma unroll
    for (int i = 0; i < 8; i++) {
        v[i] = __ldg(src + i * 32 + lane);
        ss += v[i].x * v[i].x + v[i].y * v[i].y + v[i].z * v[i].z + v[i].w * v[i].w;
    }
#pragma unroll
    for (int off = 16; off > 0; off >>= 1)
        ss += __shfl_xor_sync(0xffffffffu, ss, off);

    const float inv = 1.f / fmaxf(sqrtf(ss), EPSN);

    unsigned int* __restrict__ dst =
        (unsigned int*)(g_actn_fp8 + (size_t)row * DDIM);
#pragma unroll
    for (int i = 0; i < 8; i++) {
        float2 f01 = make_float2(v[i].x * inv, v[i].y * inv);
        float2 f23 = make_float2(v[i].z * inv, v[i].w * inv);
        __nv_fp8x2_storage_t lo = __nv_cvt_float2_to_fp8x2(f01, __NV_SATFINITE, __NV_E4M3);
        __nv_fp8x2_storage_t hi = __nv_cvt_float2_to_fp8x2(f23, __NV_SATFINITE, __NV_E4M3);
        dst[i * 32 + lane] = (unsigned int)lo | ((unsigned int)hi << 16);
    }
}

// ---------------------------------------------------------------------------
// Pass 2: one warp per (l, n) pair; gather 7 normalized e4m3 rows, 6 dots.
// Row = 1024 B = 64 uint4; 32 lanes x 2 iters, coalesced 2048B/warp-iter.
// The 24 MiB fp8 buffer is fully L2-resident -> L2-bandwidth bound (~16 us).
// Byte-offset addressing off one base pointer keeps address math in 32-bit
// regs, lowering register pressure.
// ---------------------------------------------------------------------------
__device__ __forceinline__ void unpack16(const uint4 u, float2* f /*8 float2*/)
{
    const unsigned short* s = (const unsigned short*)&u;   // 8 fp8x2 packs
#pragma unroll
    for (int q = 0; q < 8; q++) {
        __half2_raw hr = __nv_cvt_fp8x2_to_halfraw2((__nv_fp8x2_storage_t)s[q], __NV_E4M3);
        f[q] = __half22float2(*(const __half2*)&hr);
    }
}

__global__ void __launch_bounds__(256)
mi_dot_kernel(const int* __restrict__ anchor_idx,
              const int* __restrict__ pos_idx,
              const int* __restrict__ neg_idx)
{
    const int gw   = (blockIdx.x * blockDim.x + threadIdx.x) >> 5;  // global warp
    const int lane = threadIdx.x & 31;
    if (gw >= TOTAL_PAIRS) return;

    const int l = gw / NPAIR;
    const int n = gw - l * NPAIR;

    const char* __restrict__ base =
        (const char*)g_actn_fp8 + (size_t)l * (BS * DDIM);

    // 32-bit byte offsets within a layer (2048 rows * 1024 B = 2 MiB).
    unsigned int offA = (unsigned int)__ldg(anchor_idx + n) << 10;
    unsigned int offP = (unsigned int)__ldg(pos_idx + n)    << 10;
    unsigned int offN[KNEG];
#pragma unroll
    for (int k = 0; k < KNEG; k++)
        offN[k] = (unsigned int)__ldg(neg_idx + n * KNEG + k) << 10;

    float ap = 0.f;
    float an[KNEG] = {0.f, 0.f, 0.f, 0.f, 0.f};

#pragma unroll
    for (int i = 0; i < 2; i++) {
        const unsigned int jb = (unsigned int)(i * 32 + lane) * 16u;  // byte offset

        // Issue all 7 independent loads up front (MLP).
        const uint4 au = __ldg((const uint4*)(base + offA + jb));
        const uint4 pu = __ldg((const uint4*)(base + offP + jb));
        uint4 nu[KNEG];
#pragma unroll
        for (int k = 0; k < KNEG; k++)
            nu[k] = __ldg((const uint4*)(base + offN[k] + jb));

        // Unpack anchor once (16 elems), reuse for all 6 dots.
        float2 av[8];
        unpack16(au, av);

        {
            float2 f[8];
            unpack16(pu, f);
#pragma unroll
            for (int q = 0; q < 8; q++)
                ap += av[q].x * f[q].x + av[q].y * f[q].y;
        }
#pragma unroll
        for (int k = 0; k < KNEG; k++) {
            float2 f[8];
            unpack16(nu[k], f);
#pragma unroll
            for (int q = 0; q < 8; q++)
                an[k] += av[q].x * f[q].x + av[q].y * f[q].y;
        }
    }

    // Warp-reduce the 6 dot products.
#pragma unroll
    for (int off = 16; off > 0; off >>= 1) {
        ap += __shfl_xor_sync(0xffffffffu, ap, off);
#pragma unroll
        for (int k = 0; k < KNEG; k++)
            an[k] += __shfl_xor_sync(0xffffffffu, an[k], off);
    }

    if (lane == 0) {
        const float pos_sim = ap * INV_TEMP;
        float denom = expf(pos_sim);
#pragma unroll
        for (int k = 0; k < KNEG; k++)
            denom += expf(an[k] * INV_TEMP);
        // log(exp(pos)/denom) = pos - log(denom)
        g_contrib[gw] = pos_sim - logf(denom);
    }
}

// ---------------------------------------------------------------------------
// Pass 3: deterministic fixed-order reduction to the scalar loss.
// mean-over-n then mean-over-l == flat mean (N identical per layer).
// ---------------------------------------------------------------------------
__global__ void __launch_bounds__(1024)
mi_reduce_kernel(float* __restrict__ out)
{
    __shared__ float sm[1024];
    float s = 0.f;
    for (int i = threadIdx.x; i < TOTAL_PAIRS; i += 1024)
        s += g_contrib[i];
    sm[threadIdx.x] = s;
    __syncthreads();
#pragma unroll
    for (int off = 512; off > 0; off >>= 1) {
        if (threadIdx.x < off) sm[threadIdx.x] += sm[threadIdx.x + off];
        __syncthreads();
    }
    if (threadIdx.x == 0)
        out[0] = -sm[0] * (1.0f / (float)TOTAL_PAIRS);
}

extern "C" void kernel_launch(void* const* d_in, const int* in_sizes, int n_in,
                              void* d_out, int out_size)
{
    const float* act        = (const float*)d_in[0];
    const int*   anchor_idx = (const int*)d_in[1];
    const int*   pos_idx    = (const int*)d_in[2];
    const int*   neg_idx    = (const int*)d_in[3];
    float*       out        = (float*)d_out;

    // Pass 1: one warp per row -> 24576 warps, 8 warps/block.
    norm_cvt_kernel<<<(TOTAL_ROWS * 32) / 256, 256>>>(act);

    // Pass 2: one warp per pair -> 24576 warps, 8 warps/block.
    mi_dot_kernel<<<(TOTAL_PAIRS * 32) / 256, 256>>>(anchor_idx, pos_idx, neg_idx);

    // Pass 3.
    mi_reduce_kernel<<<1, 1024>>>(out);
}

// round 10
// speedup vs baseline: 1.2508x; 1.2508x over previous
#include <cuda_runtime.h>
#include <cuda_bf16.h>
#include <cuda_fp8.h>
#include <cuda_fp16.h>
#include <math.h>

// Problem constants (fixed shapes from reference)
#define NLAYER   12
#define BS       2048          // B*S
#define DDIM     1024
#define NPAIR    2048
#define KNEG     5
#define INV_TEMP 10.0f         // 1 / 0.1
#define EPSN     1e-8f
#define TOTAL_PAIRS (NLAYER * NPAIR)                 // 24576
#define TOTAL_ROWS  (NLAYER * BS)                    // 24576 rows of 1024
#define TOTAL_ELEMS ((size_t)TOTAL_ROWS * DDIM)      // 25,165,824

// Static scratch (no runtime allocation).
__device__ unsigned char g_actn_fp8[TOTAL_ELEMS];    // normalized rows, e4m3, 24 MiB
__device__ float         g_contrib[TOTAL_PAIRS];     // per-(l,n) loss terms

// ---------------------------------------------------------------------------
// Pass 1: per-row L2-normalize in fp32 (exact), round unit vector to e4m3.
// One warp per row; 32 lanes x 8 float4, coalesced. HBM-streaming bound
// (measured 19.9us @ 69.3% DRAM). __ldcs on the fp32 stream: evict-first,
// so the e4m3 writes stay L2-resident for pass 2.
// ---------------------------------------------------------------------------
__global__ void __launch_bounds__(256)
norm_cvt_kernel(const float* __restrict__ act)
{
    const int row  = (blockIdx.x * blockDim.x + threadIdx.x) >> 5;
    const int lane = threadIdx.x & 31;
    if (row >= TOTAL_ROWS) return;

    const float4* __restrict__ src = (const float4*)(act + (size_t)row * DDIM);

    float4 v[8];
    float ss = 0.f;
#pragma unroll
    for (int i = 0; i < 8; i++) {
        v[i] = __ldcs(src + i * 32 + lane);
        ss += v[i].x * v[i].x + v[i].y * v[i].y + v[i].z * v[i].z + v[i].w * v[i].w;
    }
#pragma unroll
    for (int off = 16; off > 0; off >>= 1)
        ss += __shfl_xor_sync(0xffffffffu, ss, off);

    const float inv = 1.f / fmaxf(sqrtf(ss), EPSN);

    unsigned int* __restrict__ dst =
        (unsigned int*)(g_actn_fp8 + (size_t)row * DDIM);
#pragma unroll
    for (int i = 0; i < 8; i++) {
        float2 f01 = make_float2(v[i].x * inv, v[i].y * inv);
        float2 f23 = make_float2(v[i].z * inv, v[i].w * inv);
        __nv_fp8x2_storage_t lo = __nv_cvt_float2_to_fp8x2(f01, __NV_SATFINITE, __NV_E4M3);
        __nv_fp8x2_storage_t hi = __nv_cvt_float2_to_fp8x2(f23, __NV_SATFINITE, __NV_E4M3);
        dst[i * 32 + lane] = (unsigned int)lo | ((unsigned int)hi << 16);
    }
}

// ---------------------------------------------------------------------------
// Pass 2: one warp per (l, n) pair; gather 7 e4m3 rows, 6 dots.
// fp8x2 -> half2 (one cvt) then HFMA2 accumulate: ~16 instr per uint4 vs ~40
// for the float path. Per-lane half accumulators see only 16 products of
// magnitude ~1e-3 (no overflow; rounding noise ~6e-4/logit, 10x below the
// e4m3 noise floor). Cross-lane reduction in fp32.
// ---------------------------------------------------------------------------
__device__ __forceinline__ void unpack16h(const uint4 u, __half2* h /*8*/)
{
    const unsigned short* s = (const unsigned short*)&u;   // 8 fp8x2 packs
#pragma unroll
    for (int q = 0; q < 8; q++) {
        __half2_raw hr = __nv_cvt_fp8x2_to_halfraw2((__nv_fp8x2_storage_t)s[q], __NV_E4M3);
        h[q] = *(const __half2*)&hr;
    }
}

__global__ void __launch_bounds__(256)
mi_dot_kernel(const int* __restrict__ anchor_idx,
              const int* __restrict__ pos_idx,
              const int* __restrict__ neg_idx)
{
    const int gw   = (blockIdx.x * blockDim.x + threadIdx.x) >> 5;  // global warp
    const int lane = threadIdx.x & 31;
    if (gw >= TOTAL_PAIRS) return;

    const int l = gw / NPAIR;
    const int n = gw - l * NPAIR;

    const char* __restrict__ base =
        (const char*)g_actn_fp8 + (size_t)l * (BS * DDIM);

    // 32-bit byte offsets within a layer (2048 rows * 1024 B = 2 MiB).
    unsigned int offA = (unsigned int)__ldg(anchor_idx + n) << 10;
    unsigned int offP = (unsigned int)__ldg(pos_idx + n)    << 10;
    unsigned int offN[KNEG];
#pragma unroll
    for (int k = 0; k < KNEG; k++)
        offN[k] = (unsigned int)__ldg(neg_idx + n * KNEG + k) << 10;

    const __half2 hz = __float2half2_rn(0.f);
    __half2 accP = hz;
    __half2 accN[KNEG] = {hz, hz, hz, hz, hz};

#pragma unroll
    for (int i = 0; i < 2; i++) {
        const unsigned int jb = (unsigned int)(i * 32 + lane) * 16u;  // byte offset

        // Issue all 7 independent loads up front (MLP).
        const uint4 au = __ldg((const uint4*)(base + offA + jb));
        const uint4 pu = __ldg((const uint4*)(base + offP + jb));
        uint4 nu[KNEG];
#pragma unroll
        for (int k = 0; k < KNEG; k++)
            nu[k] = __ldg((const uint4*)(base + offN[k] + jb));

        // Unpack anchor once (16 elems), reuse for all 6 dots.
        __half2 ah[8];
        unpack16h(au, ah);

        {
            __half2 h[8];
            unpack16h(pu, h);
#pragma unroll
            for (int q = 0; q < 8; q++)
                accP = __hfma2(ah[q], h[q], accP);
        }
#pragma unroll
        for (int k = 0; k < KNEG; k++) {
            __half2 h[8];
            unpack16h(nu[k], h);
#pragma unroll
            for (int q = 0; q < 8; q++)
                accN[k] = __hfma2(ah[q], h[q], accN[k]);
        }
    }

    // To fp32, then warp-reduce the 6 dot products.
    float ap = __low2float(accP) + __high2float(accP);
    float an[KNEG];
#pragma unroll
    for (int k = 0; k < KNEG; k++)
        an[k] = __low2float(accN[k]) + __high2float(accN[k]);

#pragma unroll
    for (int off = 16; off > 0; off >>= 1) {
        ap += __shfl_xor_sync(0xffffffffu, ap, off);
#pragma unroll
        for (int k = 0; k < KNEG; k++)
            an[k] += __shfl_xor_sync(0xffffffffu, an[k], off);
    }

    if (lane == 0) {
        const float pos_sim = ap * INV_TEMP;
        float denom = expf(pos_sim);
#pragma unroll
        for (int k = 0; k < KNEG; k++)
            denom += expf(an[k] * INV_TEMP);
        // log(exp(pos)/denom) = pos - log(denom)
        g_contrib[gw] = pos_sim - logf(denom);
    }
}

// ---------------------------------------------------------------------------
// Pass 3: deterministic fixed-order reduction to the scalar loss.
// ---------------------------------------------------------------------------
__global__ void __launch_bounds__(1024)
mi_reduce_kernel(float* __restrict__ out)
{
    __shared__ float sm[1024];
    float s = 0.f;
    for (int i = threadIdx.x; i < TOTAL_PAIRS; i += 1024)
        s += g_contrib[i];
    sm[threadIdx.x] = s;
    __syncthreads();
#pragma unroll
    for (int off = 512; off > 0; off >>= 1) {
        if (threadIdx.x < off) sm[threadIdx.x] += sm[threadIdx.x + off];
        __syncthreads();
    }
    if (threadIdx.x == 0)
        out[0] = -sm[0] * (1.0f / (float)TOTAL_PAIRS);
}

extern "C" void kernel_launch(void* const* d_in, const int* in_sizes, int n_in,
                              void* d_out, int out_size)
{
    const float* act        = (const float*)d_in[0];
    const int*   anchor_idx = (const int*)d_in[1];
    const int*   pos_idx    = (const int*)d_in[2];
    const int*   neg_idx    = (const int*)d_in[3];
    float*       out        = (float*)d_out;

    // Pass 1: one warp per row -> 24576 warps, 8 warps/block.
    norm_cvt_kernel<<<(TOTAL_ROWS * 32) / 256, 256>>>(act);

    // Pass 2: one warp per pair -> 24576 warps, 8 warps/block.
    mi_dot_kernel<<<(TOTAL_PAIRS * 32) / 256, 256>>>(anchor_idx, pos_idx, neg_idx);

    // Pass 3.
    mi_reduce_kernel<<<1, 1024>>>(out);
}